// round 13
// baseline (speedup 1.0000x reference)
#include <cuda_runtime.h>

#define NB    32
#define NC    3
#define NT    128000
#define NT4   (NT/4)        // 32000 float4 per (b,c)
#define TSUB  1000
#define TF    8000
#define NBLK  16            // moment blocks per batch
#define TPB   256
#define NQ    21            // 3 sum_x + 3 sum_y + 9 sum_xy + 3 sum_xx + 3 sum_yy
#define EPSF  1e-8f
#define FULLM 0xffffffffu
#define MOM_T (NB * NBLK)        // 512 moment blocks
#define GRID  (MOM_T + NB)       // + 32 diar/epilogue blocks = 544 (< 592, one wave)

// partials: [batch][stat q][slot] — per-lane contiguous for the epilogue
__device__ float g_part2[NB * NQ * NBLK];
__device__ float g_res_s[NB], g_res_d[NB], g_res_e[NB];
__device__ int   g_cnt[NB];      // per-batch moment publishes (16 each)
__device__ int   g_done;         // batches finished; combiner resets all

__device__ __forceinline__ float warp_sum(float v) {
#pragma unroll
    for (int o = 16; o > 0; o >>= 1) v += __shfl_down_sync(FULLM, v, o);
    return v;
}

// release-increment WITHOUT a fence instruction (no CCTL.IVALL, no L1 flush)
__device__ __forceinline__ void red_release(int* p) {
    asm volatile("red.release.gpu.global.add.s32 [%0], 1;" :: "l"(p) : "memory");
}
__device__ __forceinline__ int ld_acquire(const int* p) {
    int c;
    asm volatile("ld.acquire.gpu.global.s32 %0, [%1];" : "=r"(c) : "l"(p) : "memory");
    return c;
}
__device__ __forceinline__ int atom_acqrel_inc(int* p) {
    int r;
    asm volatile("atom.acq_rel.gpu.global.add.s32 %0, [%1], 1;"
                 : "=r"(r) : "l"(p) : "memory");
    return r;
}

__global__ void __launch_bounds__(TPB)
fused_kernel(const float* __restrict__ sep, const float* __restrict__ src,
             const float* __restrict__ diar, const float* __restrict__ labels,
             const float* __restrict__ exist, const int* __restrict__ nspk,
             float* __restrict__ out)
{
    const int blk  = blockIdx.x;
    const int tid  = threadIdx.x;
    const int lane = tid & 31;
    const int warp = tid >> 5;
    __shared__ float sm[TPB / 32][NQ];

    if (blk < MOM_T) {
        // ================= streaming moment accumulation over T =============
        const int b  = blk / NBLK;
        const int bb = blk % NBLK;
        const float4* x0 = (const float4*)(sep + (size_t)(b * 3 + 0) * NT);
        const float4* x1 = (const float4*)(sep + (size_t)(b * 3 + 1) * NT);
        const float4* x2 = (const float4*)(sep + (size_t)(b * 3 + 2) * NT);
        const float4* y0 = (const float4*)(src + (size_t)(b * 3 + 0) * NT);
        const float4* y1 = (const float4*)(src + (size_t)(b * 3 + 1) * NT);
        const float4* y2 = (const float4*)(src + (size_t)(b * 3 + 2) * NT);
        const int chunk = NT4 / NBLK;      // 2000
        const int lo = bb * chunk;
        const int hi = lo + chunk;

        float acc[NQ];
#pragma unroll
        for (int q = 0; q < NQ; q++) acc[q] = 0.f;

        for (int i = lo + tid; i < hi; i += TPB) {
            float4 a0 = x0[i], a1 = x1[i], a2 = x2[i];
            float4 c0 = y0[i], c1 = y1[i], c2 = y2[i];
            const float* pa0 = (const float*)&a0;
            const float* pa1 = (const float*)&a1;
            const float* pa2 = (const float*)&a2;
            const float* pc0 = (const float*)&c0;
            const float* pc1 = (const float*)&c1;
            const float* pc2 = (const float*)&c2;
#pragma unroll
            for (int k = 0; k < 4; k++) {
                float xa = pa0[k], xb = pa1[k], xc = pa2[k];
                float ya = pc0[k], yb = pc1[k], yc = pc2[k];
                acc[0]  += xa;      acc[1]  += xb;      acc[2]  += xc;
                acc[3]  += ya;      acc[4]  += yb;      acc[5]  += yc;
                acc[6]  += xa * ya; acc[7]  += xa * yb; acc[8]  += xa * yc;
                acc[9]  += xb * ya; acc[10] += xb * yb; acc[11] += xb * yc;
                acc[12] += xc * ya; acc[13] += xc * yb; acc[14] += xc * yc;
                acc[15] += xa * xa; acc[16] += xb * xb; acc[17] += xc * xc;
                acc[18] += ya * ya; acc[19] += yb * yb; acc[20] += yc * yc;
            }
        }
#pragma unroll
        for (int q = 0; q < NQ; q++) {
            float v = warp_sum(acc[q]);
            if (lane == 0) sm[warp][q] = v;
        }
        __syncthreads();
        if (warp == 0 && lane < NQ) {
            float s = 0.f;
#pragma unroll
            for (int w = 0; w < TPB / 32; w++) s += sm[w][lane];
            g_part2[(b * NQ + lane) * NBLK + bb] = s;
        }
        // publish (release, fence-free). syncthreads orders warp0's stores first.
        __syncthreads();
        if (tid == 0) red_release(&g_cnt[b]);
        return;
    }

    // ================= diar + per-batch epilogue block (one per batch) ======
    const int b = blk - MOM_T;
    __shared__ float sm_D[9];

    {
        const float* dp = diar   + (size_t)b * TSUB * 3;
        const float* lb = labels + (size_t)b * TF * 3;
        float acc[9];
#pragma unroll
        for (int q = 0; q < 9; q++) acc[q] = 0.f;

        for (int t = tid; t < TSUB; t += TPB) {
            float p0 = dp[t * 3 + 0], p1 = dp[t * 3 + 1], p2 = dp[t * 3 + 2];
            // idx = floor(t * (8000/1000)) = 8t
            float l0 = lb[t * 24 + 0], l1 = lb[t * 24 + 1], l2 = lb[t * 24 + 2];
            float lp0 = fmaxf(__logf(p0), -100.f);
            float lp1 = fmaxf(__logf(p1), -100.f);
            float lp2 = fmaxf(__logf(p2), -100.f);
            float lq0 = fmaxf(__logf(1.f - p0), -100.f);
            float lq1 = fmaxf(__logf(1.f - p1), -100.f);
            float lq2 = fmaxf(__logf(1.f - p2), -100.f);
            float m0 = 1.f - l0, m1 = 1.f - l1, m2 = 1.f - l2;
            acc[0] += lp0 * l0 + lq0 * m0;
            acc[1] += lp0 * l1 + lq0 * m1;
            acc[2] += lp0 * l2 + lq0 * m2;
            acc[3] += lp1 * l0 + lq1 * m0;
            acc[4] += lp1 * l1 + lq1 * m1;
            acc[5] += lp1 * l2 + lq1 * m2;
            acc[6] += lp2 * l0 + lq2 * m0;
            acc[7] += lp2 * l1 + lq2 * m1;
            acc[8] += lp2 * l2 + lq2 * m2;
        }
#pragma unroll
        for (int q = 0; q < 9; q++) {
            float v = warp_sum(acc[q]);
            if (lane == 0) sm[warp][q] = v;
        }
        __syncthreads();
        if (warp == 0 && lane < 9) {
            float s = 0.f;
#pragma unroll
            for (int w = 0; w < TPB / 32; w++) s += sm[w][lane];
            sm_D[lane] = s;          // stays in shared — epilogue is local
        }
        __syncthreads();             // all warps: sm_D ready; warps 1..7 done
    }
    if (warp != 0) return;

    // ---- warp 0: wait for this batch's 16 moment publishes (acquire) ----
    if (lane == 0) {
        while (ld_acquire(&g_cnt[b]) < NBLK) { }
    }
    __syncwarp();

    // ---- lane-parallel epilogue (proven R3 scheme) ----
    const int q = min(lane, NQ - 1);
    float sq = 0.f;
    {
        const float* base = g_part2 + (size_t)(b * NQ + q) * NBLK;
#pragma unroll
        for (int k = 0; k < NBLK; k++) sq += base[k];
    }
    const int l = min(lane, 8);
    const float dval = sm_D[l];
    const float pex  = exist[b * 4 + (lane & 3)];
    const int ns_raw = nspk[b];
    const int ns = min(max(ns_raw, 1), 3);

    const int i3 = l / 3, j3 = l % 3;
    const float fT = (float)NT;
    float sx  = __shfl_sync(FULLM, sq, i3);
    float sy  = __shfl_sync(FULLM, sq, 3 + j3);
    float sxy = __shfl_sync(FULLM, sq, 6 + l);
    float sxx = __shfl_sync(FULLM, sq, 15 + i3);
    float syy = __shfl_sync(FULLM, sq, 18 + j3);

    float mx = sx / fT, my = sy / fT;
    float estsq = sxx - fT * mx * mx;
    float tgtsq = syy - fT * my * my;
    float dotc  = sxy - fT * mx * my;
    float al  = __fdividef(dotc, tgtsq + EPSF);
    float a2t = al * al * tgtsq;
    float sig = a2t + EPSF;
    float noi = estsq - 2.f * al * dotc + a2t + EPSF;
    float S_l = 10.f * __log10f(__fdividef(sig, noi));
    float D_l = -dval * (1.f / (float)TSUB);

    // perms {012,021,102,120,201,210}, 2 bits/entry, 6 bits/perm
    const unsigned long long PP =
        0x24ULL | (0x18ULL << 6) | (0x21ULL << 12) |
        (0x09ULL << 18) | (0x12ULL << 24) | (0x06ULL << 30);
    const int p = min(lane, 5);
    bool valid = true;
    float ss = 0.f, dd = 0.f;
#pragma unroll
    for (int slot = 0; slot < 3; slot++) {
        int pi = (int)((PP >> (p * 6 + slot * 2)) & 3ULL);
        int srci = pi * 3 + slot;
        float Sv = __shfl_sync(FULLM, S_l, srci);
        float Dv = __shfl_sync(FULLM, D_l, srci);
        if (!(pi < ns || slot >= ns)) valid = false;
        if (slot < ns) { ss += Sv; dd += Dv; }
    }
    const float inv_n = 1.f / (float)ns;
    float cand_s = valid ? -ss * inv_n : 3.4e38f;
    float cand_d = valid ?  dd * inv_n : 3.4e38f;

    float ev = 0.f;
    if (lane < 4) {
        const int nex = min(ns_raw, 3);
        float t = (lane < nex) ? 1.f : 0.f;
        ev = -(t * fmaxf(__logf(pex), -100.f) +
               (1.f - t) * fmaxf(__logf(1.f - pex), -100.f));
    }

#pragma unroll
    for (int o = 16; o > 0; o >>= 1) {
        cand_s = fminf(cand_s, __shfl_xor_sync(FULLM, cand_s, o));
        cand_d = fminf(cand_d, __shfl_xor_sync(FULLM, cand_d, o));
        ev    += __shfl_xor_sync(FULLM, ev, o);
    }

    if (lane == 0) {
        g_res_s[b] = cand_s;
        g_res_d[b] = cand_d;
        g_res_e[b] = ev;
    }
    __syncwarp();

    // publish batch result; the 32nd publisher combines (acq_rel atomic)
    int prev = 0;
    if (lane == 0) prev = atom_acqrel_inc(&g_done);
    prev = __shfl_sync(FULLM, prev, 0);
    if (prev == NB - 1) {
        float rs = warp_sum(g_res_s[lane]);
        float rd = warp_sum(g_res_d[lane]);
        float re = warp_sum(g_res_e[lane]);
        g_cnt[lane] = 0;             // reset for the next (deterministic) replay
        if (lane == 0) {
            g_done = 0;
            float loss_sisnr = rs * (1.f / (float)NB);
            float loss_diar  = rd * (1.f / (float)NB);
            float loss_exist = re * (1.f / (float)(NB * 4));
            float total = loss_sisnr + 0.2f * loss_diar + 0.2f * loss_exist;
            out[0] = total;
            out[1] = loss_sisnr;
            out[2] = loss_diar;
            out[3] = loss_exist;
            out[4] = -loss_sisnr;    // mean_sisnr == -loss_sisnr exactly
        }
    }
}

extern "C" void kernel_launch(void* const* d_in, const int* in_sizes, int n_in,
                              void* d_out, int out_size)
{
    const float* sep = nullptr;
    const float* src = nullptr;
    const float* diar = nullptr;
    const float* lab = nullptr;
    const float* ex = nullptr;
    const int*   ns = nullptr;

    for (int i = 0; i < n_in; i++) {
        switch (in_sizes[i]) {
            case NB * NC * NT:       // 12,288,000: separated first, sources second
                if (!sep) sep = (const float*)d_in[i];
                else       src = (const float*)d_in[i];
                break;
            case NB * TSUB * NC:     // 96,000
                diar = (const float*)d_in[i]; break;
            case NB * (NC + 1):      // 128
                ex = (const float*)d_in[i]; break;
            case NB * TF * NC:       // 768,000
                lab = (const float*)d_in[i]; break;
            case NB:                 // 32
                ns = (const int*)d_in[i]; break;
            default: break;
        }
    }

    fused_kernel<<<GRID, TPB>>>(sep, src, diar, lab, ex, ns, (float*)d_out);
}

// round 15
// speedup vs baseline: 1.2553x; 1.2553x over previous
#include <cuda_runtime.h>

#define NB    32
#define NC    3
#define NT    128000
#define NT4   (NT/4)        // 32000 float4 per (b,c)
#define TSUB  1000
#define TF    8000
#define NBLK  16            // moment blocks per batch
#define TPB   256
#define NQ    21            // 3 sum_x + 3 sum_y + 9 sum_xy + 3 sum_xx + 3 sum_yy
#define EPSF  1e-8f
#define FULLM 0xffffffffu
#define GRID  (NB * NBLK + NB)   // 544 blocks

// partials: [batch][stat q][slot] — per-lane contiguous for the finalize
__device__ float g_part2[NB * NQ * NBLK];
__device__ float g_D[NB * 9];

__device__ __forceinline__ float warp_sum(float v) {
#pragma unroll
    for (int o = 16; o > 0; o >>= 1) v += __shfl_down_sync(FULLM, v, o);
    return v;
}

__global__ void __launch_bounds__(TPB)
main_kernel(const float* __restrict__ sep, const float* __restrict__ src,
            const float* __restrict__ diar, const float* __restrict__ labels)
{
    const int blk  = blockIdx.x;
    const int tid  = threadIdx.x;
    const int lane = tid & 31;
    const int warp = tid >> 5;
    __shared__ float sm[TPB / 32][NQ];

    if (blk < NB * NBLK) {
        // ---- streaming moment accumulation over T ----
        const int b  = blk / NBLK;
        const int bb = blk % NBLK;
        const float4* x0 = (const float4*)(sep + (size_t)(b * 3 + 0) * NT);
        const float4* x1 = (const float4*)(sep + (size_t)(b * 3 + 1) * NT);
        const float4* x2 = (const float4*)(sep + (size_t)(b * 3 + 2) * NT);
        const float4* y0 = (const float4*)(src + (size_t)(b * 3 + 0) * NT);
        const float4* y1 = (const float4*)(src + (size_t)(b * 3 + 1) * NT);
        const float4* y2 = (const float4*)(src + (size_t)(b * 3 + 2) * NT);
        const int chunk = NT4 / NBLK;      // 2000
        const int lo = bb * chunk;
        const int hi = lo + chunk;

        float acc[NQ];
#pragma unroll
        for (int q = 0; q < NQ; q++) acc[q] = 0.f;

        for (int i = lo + tid; i < hi; i += TPB) {
            float4 a0 = x0[i], a1 = x1[i], a2 = x2[i];
            float4 c0 = y0[i], c1 = y1[i], c2 = y2[i];
            const float* pa0 = (const float*)&a0;
            const float* pa1 = (const float*)&a1;
            const float* pa2 = (const float*)&a2;
            const float* pc0 = (const float*)&c0;
            const float* pc1 = (const float*)&c1;
            const float* pc2 = (const float*)&c2;
#pragma unroll
            for (int k = 0; k < 4; k++) {
                float xa = pa0[k], xb = pa1[k], xc = pa2[k];
                float ya = pc0[k], yb = pc1[k], yc = pc2[k];
                acc[0]  += xa;      acc[1]  += xb;      acc[2]  += xc;
                acc[3]  += ya;      acc[4]  += yb;      acc[5]  += yc;
                acc[6]  += xa * ya; acc[7]  += xa * yb; acc[8]  += xa * yc;
                acc[9]  += xb * ya; acc[10] += xb * yb; acc[11] += xb * yc;
                acc[12] += xc * ya; acc[13] += xc * yb; acc[14] += xc * yc;
                acc[15] += xa * xa; acc[16] += xb * xb; acc[17] += xc * xc;
                acc[18] += ya * ya; acc[19] += yb * yb; acc[20] += yc * yc;
            }
        }
#pragma unroll
        for (int q = 0; q < NQ; q++) {
            float v = warp_sum(acc[q]);
            if (lane == 0) sm[warp][q] = v;
        }
        __syncthreads();
        if (warp == 0 && lane < NQ) {
            float s = 0.f;
#pragma unroll
            for (int w = 0; w < TPB / 32; w++) s += sm[w][lane];
            g_part2[(b * NQ + lane) * NBLK + bb] = s;
        }
    } else {
        // ---- diarization BCE matrix for one batch ----
        const int b = blk - NB * NBLK;
        const float* dp = diar   + (size_t)b * TSUB * 3;
        const float* lb = labels + (size_t)b * TF * 3;
        float acc[9];
#pragma unroll
        for (int q = 0; q < 9; q++) acc[q] = 0.f;

        for (int t = tid; t < TSUB; t += TPB) {
            float p0 = dp[t * 3 + 0], p1 = dp[t * 3 + 1], p2 = dp[t * 3 + 2];
            // idx = floor(t * (8000/1000)) = 8t
            float l0 = lb[t * 24 + 0], l1 = lb[t * 24 + 1], l2 = lb[t * 24 + 2];
            float lp0 = fmaxf(__logf(p0), -100.f);
            float lp1 = fmaxf(__logf(p1), -100.f);
            float lp2 = fmaxf(__logf(p2), -100.f);
            float lq0 = fmaxf(__logf(1.f - p0), -100.f);
            float lq1 = fmaxf(__logf(1.f - p1), -100.f);
            float lq2 = fmaxf(__logf(1.f - p2), -100.f);
            float m0 = 1.f - l0, m1 = 1.f - l1, m2 = 1.f - l2;
            acc[0] += lp0 * l0 + lq0 * m0;
            acc[1] += lp0 * l1 + lq0 * m1;
            acc[2] += lp0 * l2 + lq0 * m2;
            acc[3] += lp1 * l0 + lq1 * m0;
            acc[4] += lp1 * l1 + lq1 * m1;
            acc[5] += lp1 * l2 + lq1 * m2;
            acc[6] += lp2 * l0 + lq2 * m0;
            acc[7] += lp2 * l1 + lq2 * m1;
            acc[8] += lp2 * l2 + lq2 * m2;
        }
#pragma unroll
        for (int q = 0; q < 9; q++) {
            float v = warp_sum(acc[q]);
            if (lane == 0) sm[warp][q] = v;
        }
        __syncthreads();
        if (warp == 0 && lane < 9) {
            float s = 0.f;
#pragma unroll
            for (int w = 0; w < TPB / 32; w++) s += sm[w][lane];
            g_D[b * 9 + lane] = s;
        }
    }
}

// Finalize spread across 32 blocks (one warp each, block b = batch b).
// d_out is pre-zeroed by a memset graph node; each block atomicAdds its
// weighted share — no inter-block synchronization at all.
__global__ void __launch_bounds__(32)
finalize_kernel(const float* __restrict__ exist, const int* __restrict__ nspk,
                float* __restrict__ out)
{
    const int lane = threadIdx.x;
    const int b    = blockIdx.x;

    // ---- per-lane contiguous partial reduction: lane q sums 16 slots ----
    const int q = min(lane, NQ - 1);
    float sq = 0.f;
    {
        const float* base = g_part2 + (size_t)(b * NQ + q) * NBLK;
#pragma unroll
        for (int k = 0; k < NBLK; k++) sq += base[k];
    }
    const int l = min(lane, 8);
    const float dval = g_D[b * 9 + l];
    const float pex  = exist[b * 4 + (lane & 3)];
    const int ns_raw = nspk[b];
    const int ns = min(max(ns_raw, 1), 3);

    // ---- lane l computes S[i][j], D[i][j] for l = 3*i + j ----
    const int i3 = l / 3, j3 = l % 3;
    const float fT = (float)NT;
    float sx  = __shfl_sync(FULLM, sq, i3);
    float sy  = __shfl_sync(FULLM, sq, 3 + j3);
    float sxy = __shfl_sync(FULLM, sq, 6 + l);
    float sxx = __shfl_sync(FULLM, sq, 15 + i3);
    float syy = __shfl_sync(FULLM, sq, 18 + j3);

    float mx = sx / fT, my = sy / fT;
    float estsq = sxx - fT * mx * mx;
    float tgtsq = syy - fT * my * my;
    float dotc  = sxy - fT * mx * my;
    float al  = __fdividef(dotc, tgtsq + EPSF);
    float a2t = al * al * tgtsq;
    float sig = a2t + EPSF;
    float noi = estsq - 2.f * al * dotc + a2t + EPSF;
    float S_l = 10.f * __log10f(__fdividef(sig, noi));
    float D_l = -dval * (1.f / (float)TSUB);

    // ---- lane p evaluates permutation p ----
    // perms {012,021,102,120,201,210}, 2 bits/entry, 6 bits/perm
    const unsigned long long PP =
        0x24ULL | (0x18ULL << 6) | (0x21ULL << 12) |
        (0x09ULL << 18) | (0x12ULL << 24) | (0x06ULL << 30);
    const int p = min(lane, 5);
    bool valid = true;
    float ss = 0.f, dd = 0.f;
#pragma unroll
    for (int slot = 0; slot < 3; slot++) {
        int pi = (int)((PP >> (p * 6 + slot * 2)) & 3ULL);
        int srci = pi * 3 + slot;
        float Sv = __shfl_sync(FULLM, S_l, srci);
        float Dv = __shfl_sync(FULLM, D_l, srci);
        if (!(pi < ns || slot >= ns)) valid = false;
        if (slot < ns) { ss += Sv; dd += Dv; }
    }
    const float inv_n = 1.f / (float)ns;
    float cand_s = valid ? -ss * inv_n : 3.4e38f;
    float cand_d = valid ?  dd * inv_n : 3.4e38f;
    // lanes >=6 duplicate perm 5 -> min unaffected

    // ---- exist BCE: lanes 0..3 ----
    float ev = 0.f;
    if (lane < 4) {
        const int nex = min(ns_raw, 3);
        float t = (lane < nex) ? 1.f : 0.f;
        ev = -(t * fmaxf(__logf(pex), -100.f) +
               (1.f - t) * fmaxf(__logf(1.f - pex), -100.f));
    }

    // ---- full-warp reductions ----
#pragma unroll
    for (int o = 16; o > 0; o >>= 1) {
        cand_s = fminf(cand_s, __shfl_xor_sync(FULLM, cand_s, o));
        cand_d = fminf(cand_d, __shfl_xor_sync(FULLM, cand_d, o));
        ev    += __shfl_xor_sync(FULLM, ev, o);
    }

    // ---- accumulate weighted shares into pre-zeroed out[] ----
    if (lane == 0) {
        float sh_s = cand_s * (1.f / (float)NB);          // -> loss_sisnr
        float sh_d = cand_d * (1.f / (float)NB);          // -> loss_diar
        float sh_e = ev * (1.f / (float)(NB * 4));        // -> loss_exist
        atomicAdd(out + 0, sh_s + 0.2f * sh_d + 0.2f * sh_e);
        atomicAdd(out + 1, sh_s);
        atomicAdd(out + 2, sh_d);
        atomicAdd(out + 3, sh_e);
        atomicAdd(out + 4, -sh_s);                        // mean_sisnr
    }
}

extern "C" void kernel_launch(void* const* d_in, const int* in_sizes, int n_in,
                              void* d_out, int out_size)
{
    const float* sep = nullptr;
    const float* src = nullptr;
    const float* diar = nullptr;
    const float* lab = nullptr;
    const float* ex = nullptr;
    const int*   ns = nullptr;

    for (int i = 0; i < n_in; i++) {
        switch (in_sizes[i]) {
            case NB * NC * NT:       // 12,288,000: separated first, sources second
                if (!sep) sep = (const float*)d_in[i];
                else       src = (const float*)d_in[i];
                break;
            case NB * TSUB * NC:     // 96,000
                diar = (const float*)d_in[i]; break;
            case NB * (NC + 1):      // 128
                ex = (const float*)d_in[i]; break;
            case NB * TF * NC:       // 768,000
                lab = (const float*)d_in[i]; break;
            case NB:                 // 32
                ns = (const int*)d_in[i]; break;
            default: break;
        }
    }

    // zero the 5 outputs (graph-capturable memset node), then accumulate
    cudaMemsetAsync(d_out, 0, (size_t)out_size * sizeof(float), 0);
    main_kernel<<<GRID, TPB>>>(sep, src, diar, lab);
    finalize_kernel<<<NB, 32>>>(ex, ns, (float*)d_out);
}

// round 16
// speedup vs baseline: 1.3015x; 1.0368x over previous
#include <cuda_runtime.h>

#define NB    32
#define NC    3
#define NT    128000
#define NT4   (NT/4)        // 32000 float4 per (b,c)
#define TSUB  1000
#define TF    8000
#define NBLK  16            // moment blocks per batch
#define TPB   256
#define NQ    21            // 3 sum_x + 3 sum_y + 9 sum_xy + 3 sum_xx + 3 sum_yy
#define EPSF  1e-8f
#define FULLM 0xffffffffu
#define GRID  (NB * NBLK + NB)   // 544 blocks

// partials: [batch][stat q][slot] — per-lane contiguous for the finalize
__device__ float g_part2[NB * NQ * NBLK];
__device__ float g_D[NB * 9];
__device__ float g_res_s[NB], g_res_d[NB], g_res_e[NB];
__device__ int   g_done;         // finalize blocks arrived; last one combines+resets

__device__ __forceinline__ float warp_sum(float v) {
#pragma unroll
    for (int o = 16; o > 0; o >>= 1) v += __shfl_down_sync(FULLM, v, o);
    return v;
}

__device__ __forceinline__ int atom_acqrel_inc(int* p) {
    int r;
    asm volatile("atom.acq_rel.gpu.global.add.s32 %0, [%1], 1;"
                 : "=r"(r) : "l"(p) : "memory");
    return r;
}
__device__ __forceinline__ float ld_acquire_f(const float* p) {
    float v;
    asm volatile("ld.acquire.gpu.global.f32 %0, [%1];" : "=f"(v) : "l"(p) : "memory");
    return v;
}

__global__ void __launch_bounds__(TPB)
main_kernel(const float* __restrict__ sep, const float* __restrict__ src,
            const float* __restrict__ diar, const float* __restrict__ labels)
{
    const int blk  = blockIdx.x;
    const int tid  = threadIdx.x;
    const int lane = tid & 31;
    const int warp = tid >> 5;
    __shared__ float sm[TPB / 32][NQ];

    if (blk < NB * NBLK) {
        // ---- streaming moment accumulation over T ----
        const int b  = blk / NBLK;
        const int bb = blk % NBLK;
        const float4* x0 = (const float4*)(sep + (size_t)(b * 3 + 0) * NT);
        const float4* x1 = (const float4*)(sep + (size_t)(b * 3 + 1) * NT);
        const float4* x2 = (const float4*)(sep + (size_t)(b * 3 + 2) * NT);
        const float4* y0 = (const float4*)(src + (size_t)(b * 3 + 0) * NT);
        const float4* y1 = (const float4*)(src + (size_t)(b * 3 + 1) * NT);
        const float4* y2 = (const float4*)(src + (size_t)(b * 3 + 2) * NT);
        const int chunk = NT4 / NBLK;      // 2000
        const int lo = bb * chunk;
        const int hi = lo + chunk;

        float acc[NQ];
#pragma unroll
        for (int q = 0; q < NQ; q++) acc[q] = 0.f;

        for (int i = lo + tid; i < hi; i += TPB) {
            float4 a0 = x0[i], a1 = x1[i], a2 = x2[i];
            float4 c0 = y0[i], c1 = y1[i], c2 = y2[i];
            const float* pa0 = (const float*)&a0;
            const float* pa1 = (const float*)&a1;
            const float* pa2 = (const float*)&a2;
            const float* pc0 = (const float*)&c0;
            const float* pc1 = (const float*)&c1;
            const float* pc2 = (const float*)&c2;
#pragma unroll
            for (int k = 0; k < 4; k++) {
                float xa = pa0[k], xb = pa1[k], xc = pa2[k];
                float ya = pc0[k], yb = pc1[k], yc = pc2[k];
                acc[0]  += xa;      acc[1]  += xb;      acc[2]  += xc;
                acc[3]  += ya;      acc[4]  += yb;      acc[5]  += yc;
                acc[6]  += xa * ya; acc[7]  += xa * yb; acc[8]  += xa * yc;
                acc[9]  += xb * ya; acc[10] += xb * yb; acc[11] += xb * yc;
                acc[12] += xc * ya; acc[13] += xc * yb; acc[14] += xc * yc;
                acc[15] += xa * xa; acc[16] += xb * xb; acc[17] += xc * xc;
                acc[18] += ya * ya; acc[19] += yb * yb; acc[20] += yc * yc;
            }
        }
#pragma unroll
        for (int q = 0; q < NQ; q++) {
            float v = warp_sum(acc[q]);
            if (lane == 0) sm[warp][q] = v;
        }
        __syncthreads();
        if (warp == 0 && lane < NQ) {
            float s = 0.f;
#pragma unroll
            for (int w = 0; w < TPB / 32; w++) s += sm[w][lane];
            g_part2[(b * NQ + lane) * NBLK + bb] = s;
        }
    } else {
        // ---- diarization BCE matrix for one batch ----
        const int b = blk - NB * NBLK;
        const float* dp = diar   + (size_t)b * TSUB * 3;
        const float* lb = labels + (size_t)b * TF * 3;
        float acc[9];
#pragma unroll
        for (int q = 0; q < 9; q++) acc[q] = 0.f;

        for (int t = tid; t < TSUB; t += TPB) {
            float p0 = dp[t * 3 + 0], p1 = dp[t * 3 + 1], p2 = dp[t * 3 + 2];
            // idx = floor(t * (8000/1000)) = 8t
            float l0 = lb[t * 24 + 0], l1 = lb[t * 24 + 1], l2 = lb[t * 24 + 2];
            float lp0 = fmaxf(__logf(p0), -100.f);
            float lp1 = fmaxf(__logf(p1), -100.f);
            float lp2 = fmaxf(__logf(p2), -100.f);
            float lq0 = fmaxf(__logf(1.f - p0), -100.f);
            float lq1 = fmaxf(__logf(1.f - p1), -100.f);
            float lq2 = fmaxf(__logf(1.f - p2), -100.f);
            float m0 = 1.f - l0, m1 = 1.f - l1, m2 = 1.f - l2;
            acc[0] += lp0 * l0 + lq0 * m0;
            acc[1] += lp0 * l1 + lq0 * m1;
            acc[2] += lp0 * l2 + lq0 * m2;
            acc[3] += lp1 * l0 + lq1 * m0;
            acc[4] += lp1 * l1 + lq1 * m1;
            acc[5] += lp1 * l2 + lq1 * m2;
            acc[6] += lp2 * l0 + lq2 * m0;
            acc[7] += lp2 * l1 + lq2 * m1;
            acc[8] += lp2 * l2 + lq2 * m2;
        }
#pragma unroll
        for (int q = 0; q < 9; q++) {
            float v = warp_sum(acc[q]);
            if (lane == 0) sm[warp][q] = v;
        }
        __syncthreads();
        if (warp == 0 && lane < 9) {
            float s = 0.f;
#pragma unroll
            for (int w = 0; w < TPB / 32; w++) s += sm[w][lane];
            g_D[b * 9 + lane] = s;
        }
    }
}

// Finalize: 32 blocks (one warp each, block b = batch b); the 32nd arriver
// combines the per-batch shares and writes out[] — no memset node, no
// atomics on out, only one writer.
__global__ void __launch_bounds__(32)
finalize_kernel(const float* __restrict__ exist, const int* __restrict__ nspk,
                float* __restrict__ out)
{
    const int lane = threadIdx.x;
    const int b    = blockIdx.x;

    // ---- per-lane contiguous partial reduction: lane q sums 16 slots ----
    const int q = min(lane, NQ - 1);
    float sq = 0.f;
    {
        const float* base = g_part2 + (size_t)(b * NQ + q) * NBLK;
#pragma unroll
        for (int k = 0; k < NBLK; k++) sq += base[k];
    }
    const int l = min(lane, 8);
    const float dval = g_D[b * 9 + l];
    const float pex  = exist[b * 4 + (lane & 3)];
    const int ns_raw = nspk[b];
    const int ns = min(max(ns_raw, 1), 3);

    // ---- lane l computes S[i][j], D[i][j] for l = 3*i + j ----
    const int i3 = l / 3, j3 = l % 3;
    const float fT = (float)NT;
    float sx  = __shfl_sync(FULLM, sq, i3);
    float sy  = __shfl_sync(FULLM, sq, 3 + j3);
    float sxy = __shfl_sync(FULLM, sq, 6 + l);
    float sxx = __shfl_sync(FULLM, sq, 15 + i3);
    float syy = __shfl_sync(FULLM, sq, 18 + j3);

    float mx = sx / fT, my = sy / fT;
    float estsq = sxx - fT * mx * mx;
    float tgtsq = syy - fT * my * my;
    float dotc  = sxy - fT * mx * my;
    float al  = __fdividef(dotc, tgtsq + EPSF);
    float a2t = al * al * tgtsq;
    float sig = a2t + EPSF;
    float noi = estsq - 2.f * al * dotc + a2t + EPSF;
    float S_l = 10.f * __log10f(__fdividef(sig, noi));
    float D_l = -dval * (1.f / (float)TSUB);

    // ---- lane p evaluates permutation p ----
    // perms {012,021,102,120,201,210}, 2 bits/entry, 6 bits/perm
    const unsigned long long PP =
        0x24ULL | (0x18ULL << 6) | (0x21ULL << 12) |
        (0x09ULL << 18) | (0x12ULL << 24) | (0x06ULL << 30);
    const int p = min(lane, 5);
    bool valid = true;
    float ss = 0.f, dd = 0.f;
#pragma unroll
    for (int slot = 0; slot < 3; slot++) {
        int pi = (int)((PP >> (p * 6 + slot * 2)) & 3ULL);
        int srci = pi * 3 + slot;
        float Sv = __shfl_sync(FULLM, S_l, srci);
        float Dv = __shfl_sync(FULLM, D_l, srci);
        if (!(pi < ns || slot >= ns)) valid = false;
        if (slot < ns) { ss += Sv; dd += Dv; }
    }
    const float inv_n = 1.f / (float)ns;
    float cand_s = valid ? -ss * inv_n : 3.4e38f;
    float cand_d = valid ?  dd * inv_n : 3.4e38f;
    // lanes >=6 duplicate perm 5 -> min unaffected

    // ---- exist BCE: lanes 0..3 ----
    float ev = 0.f;
    if (lane < 4) {
        const int nex = min(ns_raw, 3);
        float t = (lane < nex) ? 1.f : 0.f;
        ev = -(t * fmaxf(__logf(pex), -100.f) +
               (1.f - t) * fmaxf(__logf(1.f - pex), -100.f));
    }

    // ---- full-warp reductions ----
#pragma unroll
    for (int o = 16; o > 0; o >>= 1) {
        cand_s = fminf(cand_s, __shfl_xor_sync(FULLM, cand_s, o));
        cand_d = fminf(cand_d, __shfl_xor_sync(FULLM, cand_d, o));
        ev    += __shfl_xor_sync(FULLM, ev, o);
    }

    // ---- publish per-batch result; 32nd arriver combines ----
    if (lane == 0) {
        g_res_s[b] = cand_s;
        g_res_d[b] = cand_d;
        g_res_e[b] = ev;
    }
    __syncwarp();
    int prev = 0;
    if (lane == 0) prev = atom_acqrel_inc(&g_done);   // releases the stores above
    prev = __shfl_sync(FULLM, prev, 0);
    if (prev == NB - 1) {
        // acquire-loads: all 31 other blocks' releases are visible via the
        // acq_rel chain on g_done
        float rs = warp_sum(ld_acquire_f(&g_res_s[lane]));
        float rd = warp_sum(ld_acquire_f(&g_res_d[lane]));
        float re = warp_sum(ld_acquire_f(&g_res_e[lane]));
        if (lane == 0) {
            g_done = 0;                  // reset for next (deterministic) replay
            float loss_sisnr = rs * (1.f / (float)NB);
            float loss_diar  = rd * (1.f / (float)NB);
            float loss_exist = re * (1.f / (float)(NB * 4));
            float total = loss_sisnr + 0.2f * loss_diar + 0.2f * loss_exist;
            out[0] = total;
            out[1] = loss_sisnr;
            out[2] = loss_diar;
            out[3] = loss_exist;
            out[4] = -loss_sisnr;        // mean_sisnr == -loss_sisnr exactly
        }
    }
}

extern "C" void kernel_launch(void* const* d_in, const int* in_sizes, int n_in,
                              void* d_out, int out_size)
{
    const float* sep = nullptr;
    const float* src = nullptr;
    const float* diar = nullptr;
    const float* lab = nullptr;
    const float* ex = nullptr;
    const int*   ns = nullptr;

    for (int i = 0; i < n_in; i++) {
        switch (in_sizes[i]) {
            case NB * NC * NT:       // 12,288,000: separated first, sources second
                if (!sep) sep = (const float*)d_in[i];
                else       src = (const float*)d_in[i];
                break;
            case NB * TSUB * NC:     // 96,000
                diar = (const float*)d_in[i]; break;
            case NB * (NC + 1):      // 128
                ex = (const float*)d_in[i]; break;
            case NB * TF * NC:       // 768,000
                lab = (const float*)d_in[i]; break;
            case NB:                 // 32
                ns = (const int*)d_in[i]; break;
            default: break;
        }
    }

    main_kernel<<<GRID, TPB>>>(sep, src, diar, lab);
    finalize_kernel<<<NB, 32>>>(ex, ns, (float*)d_out);
}

// round 17
// speedup vs baseline: 1.3748x; 1.0563x over previous
#include <cuda_runtime.h>

#define NB    32
#define NC    3
#define NT    128000
#define NT4   (NT/4)        // 32000 float4 per (b,c)
#define TSUB  1000
#define TF    8000
#define NBLK  16            // moment blocks per batch
#define TPB   256
#define NQ    21            // 3 sum_x + 3 sum_y + 9 sum_xy + 3 sum_xx + 3 sum_yy
#define EPSF  1e-8f
#define FULLM 0xffffffffu
#define GRID  (NB * NBLK + NB)   // 544 blocks

// partials: [batch][stat q][slot] — per-lane contiguous for the finalize
__device__ float g_part2[NB * NQ * NBLK];
__device__ float g_D[NB * 9];

__device__ __forceinline__ float warp_sum(float v) {
#pragma unroll
    for (int o = 16; o > 0; o >>= 1) v += __shfl_down_sync(FULLM, v, o);
    return v;
}

__global__ void __launch_bounds__(TPB)
main_kernel(const float* __restrict__ sep, const float* __restrict__ src,
            const float* __restrict__ diar, const float* __restrict__ labels,
            float* __restrict__ out)
{
    const int blk  = blockIdx.x;
    const int tid  = threadIdx.x;
    const int lane = tid & 31;
    const int warp = tid >> 5;
    __shared__ float sm[TPB / 32][NQ];

    if (blk < NB * NBLK) {
        // ---- streaming moment accumulation over T ----
        const int b  = blk / NBLK;
        const int bb = blk % NBLK;
        const float4* x0 = (const float4*)(sep + (size_t)(b * 3 + 0) * NT);
        const float4* x1 = (const float4*)(sep + (size_t)(b * 3 + 1) * NT);
        const float4* x2 = (const float4*)(sep + (size_t)(b * 3 + 2) * NT);
        const float4* y0 = (const float4*)(src + (size_t)(b * 3 + 0) * NT);
        const float4* y1 = (const float4*)(src + (size_t)(b * 3 + 1) * NT);
        const float4* y2 = (const float4*)(src + (size_t)(b * 3 + 2) * NT);
        const int chunk = NT4 / NBLK;      // 2000
        const int lo = bb * chunk;
        const int hi = lo + chunk;

        float acc[NQ];
#pragma unroll
        for (int q = 0; q < NQ; q++) acc[q] = 0.f;

        for (int i = lo + tid; i < hi; i += TPB) {
            float4 a0 = x0[i], a1 = x1[i], a2 = x2[i];
            float4 c0 = y0[i], c1 = y1[i], c2 = y2[i];
            const float* pa0 = (const float*)&a0;
            const float* pa1 = (const float*)&a1;
            const float* pa2 = (const float*)&a2;
            const float* pc0 = (const float*)&c0;
            const float* pc1 = (const float*)&c1;
            const float* pc2 = (const float*)&c2;
#pragma unroll
            for (int k = 0; k < 4; k++) {
                float xa = pa0[k], xb = pa1[k], xc = pa2[k];
                float ya = pc0[k], yb = pc1[k], yc = pc2[k];
                acc[0]  += xa;      acc[1]  += xb;      acc[2]  += xc;
                acc[3]  += ya;      acc[4]  += yb;      acc[5]  += yc;
                acc[6]  += xa * ya; acc[7]  += xa * yb; acc[8]  += xa * yc;
                acc[9]  += xb * ya; acc[10] += xb * yb; acc[11] += xb * yc;
                acc[12] += xc * ya; acc[13] += xc * yb; acc[14] += xc * yc;
                acc[15] += xa * xa; acc[16] += xb * xb; acc[17] += xc * xc;
                acc[18] += ya * ya; acc[19] += yb * yb; acc[20] += yc * yc;
            }
        }
#pragma unroll
        for (int q = 0; q < NQ; q++) {
            float v = warp_sum(acc[q]);
            if (lane == 0) sm[warp][q] = v;
        }
        __syncthreads();
        if (warp == 0 && lane < NQ) {
            float s = 0.f;
#pragma unroll
            for (int w = 0; w < TPB / 32; w++) s += sm[w][lane];
            g_part2[(b * NQ + lane) * NBLK + bb] = s;
        }
    } else {
        // ---- diarization BCE matrix for one batch ----
        const int b = blk - NB * NBLK;
        // last diar block zeroes out[] (stream order: main finishes before
        // finalize's atomics begin — no race, replaces the memset graph node)
        if (b == NB - 1 && tid < 5) out[tid] = 0.f;

        const float* dp = diar   + (size_t)b * TSUB * 3;
        const float* lb = labels + (size_t)b * TF * 3;
        float acc[9];
#pragma unroll
        for (int q = 0; q < 9; q++) acc[q] = 0.f;

        for (int t = tid; t < TSUB; t += TPB) {
            float p0 = dp[t * 3 + 0], p1 = dp[t * 3 + 1], p2 = dp[t * 3 + 2];
            // idx = floor(t * (8000/1000)) = 8t
            float l0 = lb[t * 24 + 0], l1 = lb[t * 24 + 1], l2 = lb[t * 24 + 2];
            float lp0 = fmaxf(__logf(p0), -100.f);
            float lp1 = fmaxf(__logf(p1), -100.f);
            float lp2 = fmaxf(__logf(p2), -100.f);
            float lq0 = fmaxf(__logf(1.f - p0), -100.f);
            float lq1 = fmaxf(__logf(1.f - p1), -100.f);
            float lq2 = fmaxf(__logf(1.f - p2), -100.f);
            float m0 = 1.f - l0, m1 = 1.f - l1, m2 = 1.f - l2;
            acc[0] += lp0 * l0 + lq0 * m0;
            acc[1] += lp0 * l1 + lq0 * m1;
            acc[2] += lp0 * l2 + lq0 * m2;
            acc[3] += lp1 * l0 + lq1 * m0;
            acc[4] += lp1 * l1 + lq1 * m1;
            acc[5] += lp1 * l2 + lq1 * m2;
            acc[6] += lp2 * l0 + lq2 * m0;
            acc[7] += lp2 * l1 + lq2 * m1;
            acc[8] += lp2 * l2 + lq2 * m2;
        }
#pragma unroll
        for (int q = 0; q < 9; q++) {
            float v = warp_sum(acc[q]);
            if (lane == 0) sm[warp][q] = v;
        }
        __syncthreads();
        if (warp == 0 && lane < 9) {
            float s = 0.f;
#pragma unroll
            for (int w = 0; w < TPB / 32; w++) s += sm[w][lane];
            g_D[b * 9 + lane] = s;
        }
    }
}

// Finalize spread across 32 blocks (one warp each, block b = batch b).
// out[] was zeroed by main_kernel; each block atomicAdds its weighted
// share — no inter-block synchronization, no extra graph node.
__global__ void __launch_bounds__(32)
finalize_kernel(const float* __restrict__ exist, const int* __restrict__ nspk,
                float* __restrict__ out)
{
    const int lane = threadIdx.x;
    const int b    = blockIdx.x;

    // ---- per-lane contiguous partial reduction: lane q sums 16 slots ----
    const int q = min(lane, NQ - 1);
    float sq = 0.f;
    {
        const float* base = g_part2 + (size_t)(b * NQ + q) * NBLK;
#pragma unroll
        for (int k = 0; k < NBLK; k++) sq += base[k];
    }
    const int l = min(lane, 8);
    const float dval = g_D[b * 9 + l];
    const float pex  = exist[b * 4 + (lane & 3)];
    const int ns_raw = nspk[b];
    const int ns = min(max(ns_raw, 1), 3);

    // ---- lane l computes S[i][j], D[i][j] for l = 3*i + j ----
    const int i3 = l / 3, j3 = l % 3;
    const float fT = (float)NT;
    float sx  = __shfl_sync(FULLM, sq, i3);
    float sy  = __shfl_sync(FULLM, sq, 3 + j3);
    float sxy = __shfl_sync(FULLM, sq, 6 + l);
    float sxx = __shfl_sync(FULLM, sq, 15 + i3);
    float syy = __shfl_sync(FULLM, sq, 18 + j3);

    float mx = sx / fT, my = sy / fT;
    float estsq = sxx - fT * mx * mx;
    float tgtsq = syy - fT * my * my;
    float dotc  = sxy - fT * mx * my;
    float al  = __fdividef(dotc, tgtsq + EPSF);
    float a2t = al * al * tgtsq;
    float sig = a2t + EPSF;
    float noi = estsq - 2.f * al * dotc + a2t + EPSF;
    float S_l = 10.f * __log10f(__fdividef(sig, noi));
    float D_l = -dval * (1.f / (float)TSUB);

    // ---- lane p evaluates permutation p ----
    // perms {012,021,102,120,201,210}, 2 bits/entry, 6 bits/perm
    const unsigned long long PP =
        0x24ULL | (0x18ULL << 6) | (0x21ULL << 12) |
        (0x09ULL << 18) | (0x12ULL << 24) | (0x06ULL << 30);
    const int p = min(lane, 5);
    bool valid = true;
    float ss = 0.f, dd = 0.f;
#pragma unroll
    for (int slot = 0; slot < 3; slot++) {
        int pi = (int)((PP >> (p * 6 + slot * 2)) & 3ULL);
        int srci = pi * 3 + slot;
        float Sv = __shfl_sync(FULLM, S_l, srci);
        float Dv = __shfl_sync(FULLM, D_l, srci);
        if (!(pi < ns || slot >= ns)) valid = false;
        if (slot < ns) { ss += Sv; dd += Dv; }
    }
    const float inv_n = 1.f / (float)ns;
    float cand_s = valid ? -ss * inv_n : 3.4e38f;
    float cand_d = valid ?  dd * inv_n : 3.4e38f;
    // lanes >=6 duplicate perm 5 -> min unaffected

    // ---- exist BCE: lanes 0..3 ----
    float ev = 0.f;
    if (lane < 4) {
        const int nex = min(ns_raw, 3);
        float t = (lane < nex) ? 1.f : 0.f;
        ev = -(t * fmaxf(__logf(pex), -100.f) +
               (1.f - t) * fmaxf(__logf(1.f - pex), -100.f));
    }

    // ---- full-warp reductions ----
#pragma unroll
    for (int o = 16; o > 0; o >>= 1) {
        cand_s = fminf(cand_s, __shfl_xor_sync(FULLM, cand_s, o));
        cand_d = fminf(cand_d, __shfl_xor_sync(FULLM, cand_d, o));
        ev    += __shfl_xor_sync(FULLM, ev, o);
    }

    // ---- accumulate weighted shares into pre-zeroed out[] ----
    if (lane == 0) {
        float sh_s = cand_s * (1.f / (float)NB);          // -> loss_sisnr
        float sh_d = cand_d * (1.f / (float)NB);          // -> loss_diar
        float sh_e = ev * (1.f / (float)(NB * 4));        // -> loss_exist
        atomicAdd(out + 0, sh_s + 0.2f * sh_d + 0.2f * sh_e);
        atomicAdd(out + 1, sh_s);
        atomicAdd(out + 2, sh_d);
        atomicAdd(out + 3, sh_e);
        atomicAdd(out + 4, -sh_s);                        // mean_sisnr
    }
}

extern "C" void kernel_launch(void* const* d_in, const int* in_sizes, int n_in,
                              void* d_out, int out_size)
{
    const float* sep = nullptr;
    const float* src = nullptr;
    const float* diar = nullptr;
    const float* lab = nullptr;
    const float* ex = nullptr;
    const int*   ns = nullptr;

    for (int i = 0; i < n_in; i++) {
        switch (in_sizes[i]) {
            case NB * NC * NT:       // 12,288,000: separated first, sources second
                if (!sep) sep = (const float*)d_in[i];
                else       src = (const float*)d_in[i];
                break;
            case NB * TSUB * NC:     // 96,000
                diar = (const float*)d_in[i]; break;
            case NB * (NC + 1):      // 128
                ex = (const float*)d_in[i]; break;
            case NB * TF * NC:       // 768,000
                lab = (const float*)d_in[i]; break;
            case NB:                 // 32
                ns = (const int*)d_in[i]; break;
            default: break;
        }
    }

    main_kernel<<<GRID, TPB>>>(sep, src, diar, lab, (float*)d_out);
    finalize_kernel<<<NB, 32>>>(ex, ns, (float*)d_out);
}